// round 13
// baseline (speedup 1.0000x reference)
#include <cuda_runtime.h>
#include <float.h>

#define B_ 2
#define T_ 5
#define C_ 3
#define H_ 96
#define W_ 96
#define WS_ 9
#define WT_ 1
#define PS_ 5
#define PSD_ 7
#define K_ 10
#define S0_ 4
#define NH_ (H_ / S0_)                  // 24
#define NW_ (W_ / S0_)                  // 24
#define NWP_ (NW_ / 2)                  // 12 query pairs per row
#define L_ ((2 * WT_ + 1) * WS_ * WS_)  // 243
#define LSELF_ 121
#define GRID2_ (B_ * T_ * NH_ * NWP_)   // 2880
#define HW_ (H_ * W_)                   // 9216
#define NQ_ (B_ * T_ * NH_ * NW_)       // 5760 queries total

#define TR_ 15
#define TSTR_ 19                        // 19 cols (15 + 4 for second query)
#define TPLANE_ (TR_ * TSTR_)           // 285

typedef unsigned long long u64;
#define NEG1X2_ 0xBF800000BF800000ull

__device__ __forceinline__ u64 fma2(u64 a, u64 b, u64 c) {
    u64 d;
    asm("fma.rn.f32x2 %0, %1, %2, %3;" : "=l"(d) : "l"(a), "l"(b), "l"(c));
    return d;
}
__device__ __forceinline__ float f32x2_sum(u64 v) {
    return __uint_as_float((unsigned)(v & 0xffffffffull))
         + __uint_as_float((unsigned)(v >> 32));
}
__device__ __forceinline__ int refl(int i, int n) {
    i = i < 0 ? -i : i;
    return i >= n ? 2 * (n - 1) - i : i;
}
__device__ __forceinline__ int clampi(int i, int lo, int hi) {
    return min(max(i, lo), hi);
}

__global__ void zero_out_k(float* out) { out[0] = 0.0f; }

// One (channel-half, dy) unit: 3 adjacent-dwi candidates sharing a 7-wide window.
#define UNIT(hh, dyy, cbp, qbp, A0, A1, A2) do {                               \
    const u64* crow = t8 + 2 * ((cbp) + (dyy) * TSTR_) + (hh);                 \
    const u64* qrow = t8 + 2 * ((qbp) + (dyy) * TSTR_) + (hh);                 \
    u64 v0 = crow[0],  v1 = crow[2],  v2 = crow[4],  v3 = crow[6];             \
    u64 v4 = crow[8],  v5 = crow[10], v6 = crow[12];                           \
    u64 qv, d;                                                                 \
    qv = qrow[0];                                                              \
    d = fma2(v0, NEG1X2_, qv); A0 = fma2(d, d, A0);                            \
    d = fma2(v1, NEG1X2_, qv); A1 = fma2(d, d, A1);                            \
    d = fma2(v2, NEG1X2_, qv); A2 = fma2(d, d, A2);                            \
    qv = qrow[2];                                                              \
    d = fma2(v1, NEG1X2_, qv); A0 = fma2(d, d, A0);                            \
    d = fma2(v2, NEG1X2_, qv); A1 = fma2(d, d, A1);                            \
    d = fma2(v3, NEG1X2_, qv); A2 = fma2(d, d, A2);                            \
    qv = qrow[4];                                                              \
    d = fma2(v2, NEG1X2_, qv); A0 = fma2(d, d, A0);                            \
    d = fma2(v3, NEG1X2_, qv); A1 = fma2(d, d, A1);                            \
    d = fma2(v4, NEG1X2_, qv); A2 = fma2(d, d, A2);                            \
    qv = qrow[6];                                                              \
    d = fma2(v3, NEG1X2_, qv); A0 = fma2(d, d, A0);                            \
    d = fma2(v4, NEG1X2_, qv); A1 = fma2(d, d, A1);                            \
    d = fma2(v5, NEG1X2_, qv); A2 = fma2(d, d, A2);                            \
    qv = qrow[8];                                                              \
    d = fma2(v4, NEG1X2_, qv); A0 = fma2(d, d, A0);                            \
    d = fma2(v5, NEG1X2_, qv); A1 = fma2(d, d, A1);                            \
    d = fma2(v6, NEG1X2_, qv); A2 = fma2(d, d, A2);                            \
} while (0)

#define DO_GROUP(cbp, qbp, A0, A1, A2)                                         \
    if (grp == 0)      { UNIT(0, 0, cbp, qbp, A0, A1, A2);                     \
                         UNIT(0, 1, cbp, qbp, A0, A1, A2);                     \
                         UNIT(0, 2, cbp, qbp, A0, A1, A2);                     \
                         UNIT(0, 3, cbp, qbp, A0, A1, A2); }                   \
    else if (grp == 1) { UNIT(0, 4, cbp, qbp, A0, A1, A2);                     \
                         UNIT(1, 0, cbp, qbp, A0, A1, A2);                     \
                         UNIT(1, 1, cbp, qbp, A0, A1, A2); }                   \
    else               { UNIT(1, 2, cbp, qbp, A0, A1, A2);                     \
                         UNIT(1, 3, cbp, qbp, A0, A1, A2);                     \
                         UNIT(1, 4, cbp, qbp, A0, A1, A2); }

__global__ __launch_bounds__(256, 6) void dnls_main_k(
    const float* __restrict__ noisy,
    const float* __restrict__ deno,
    float* __restrict__ out)
{
    const int blk = blockIdx.x;
    const int b = blk / (T_ * NH_ * NWP_);
    int rem = blk % (T_ * NH_ * NWP_);
    const int qt = rem / (NH_ * NWP_);
    rem = rem % (NH_ * NWP_);
    const int qh  = (rem / NWP_) * S0_;
    const int qw0 = (rem % NWP_) * 8;     // queries at qw0 and qw0+4
    const int tid = threadIdx.x;
    const int wid = tid >> 5;
    const int lane = tid & 31;

    __shared__ float4 tile4 [3 * TPLANE_];   // noisy {c0,c1,c2,0}: [slot][15][19]
    __shared__ float4 dtile4[TPLANE_];       // deno frame qt
    __shared__ float  dsm[2 * L_];           // per-query distances
    __shared__ int    sel[2][K_];
    __shared__ int    kbarr[2][K_ - 1];
    __shared__ int    selt[2][K_ - 1], selh[2][K_ - 1], selw[2][K_ - 1];
    __shared__ float  red[8];

    const float* nb = noisy + (size_t)b * T_ * C_ * HW_;
    const float* db = deno  + (size_t)b * T_ * C_ * HW_;

    const int rlo = max(0, qh - 7);
    const int clo = max(0, qw0 - 7);
    const int Rn = min(H_ - 1, qh + 7) - rlo + 1;
    const int Cn = min(W_ - 1, qw0 + 4 + 7) - clo + 1;

    const bool interior = (qh >= 8 && qh <= 88 && qw0 >= 8 && qw0 <= 80);

    // carried across the phase-1 combine (interior)
    float s0 = 0, s1 = 0, s2 = 0, t0 = 0, t1 = 0, t2 = 0;
    int cand0 = -1, grp = -1;

    if (interior) {
        // ---- Fast staging: 15x19, no bounds checks ----
        for (int idx = tid; idx < TPLANE_; idx += 256) {
            int rr = idx / TSTR_, cc = idx % TSTR_;
            int gb = (rlo + rr) * W_ + clo + cc;
            #pragma unroll
            for (int s = 0; s < 3; s++) {
                int ft = clampi(qt + s - WT_, 0, T_ - 1);
                const float* base = nb + (size_t)ft * C_ * HW_ + gb;
                tile4[s * TPLANE_ + idx] =
                    make_float4(__ldg(base), __ldg(base + HW_), __ldg(base + 2 * HW_), 0.0f);
            }
            const float* dbase = db + (size_t)qt * C_ * HW_ + gb;
            dtile4[idx] =
                make_float4(__ldg(dbase), __ldg(dbase + HW_), __ldg(dbase + 2 * HW_), 0.0f);
        }
        __syncthreads();

        // ---- Phase 1: 243 threads x 2 tasks (q0 then q1, same group/triple) ----
        if (tid < 243) {
            grp = (tid < 81) ? 0 : (tid < 162 ? 1 : 2);
            const int r   = tid - grp * 81;
            const int dti = r / 27;
            const int rr  = r % 27;
            const int dhi = rr / 3;
            const int wg  = rr % 3;
            cand0 = dti * 81 + dhi * 9 + 3 * wg;

            const u64* t8 = reinterpret_cast<const u64*>(tile4);
            const int cb0 = dti * TPLANE_ + (dhi + 1) * TSTR_ + (3 * wg + 1);
            const int qb0 = 1 * TPLANE_ + 5 * TSTR_ + 5;

            u64 a0 = 0ull, a1 = 0ull, a2 = 0ull;
            DO_GROUP(cb0, qb0, a0, a1, a2);
            s0 = f32x2_sum(a0); s1 = f32x2_sum(a1); s2 = f32x2_sum(a2);

            u64 b0 = 0ull, b1 = 0ull, b2 = 0ull;
            DO_GROUP(cb0 + 4, qb0 + 4, b0, b1, b2);
            t0 = f32x2_sum(b0); t1 = f32x2_sum(b1); t2 = f32x2_sum(b2);

            if (grp == 0) {
                dsm[cand0 + 0] = s0;  dsm[cand0 + 1] = s1;  dsm[cand0 + 2] = s2;
                dsm[L_ + cand0 + 0] = t0;  dsm[L_ + cand0 + 1] = t1;  dsm[L_ + cand0 + 2] = t2;
            }
        }
        __syncthreads();
        if (grp == 1) {
            dsm[cand0 + 0] += s0;  dsm[cand0 + 1] += s1;  dsm[cand0 + 2] += s2;
            dsm[L_ + cand0 + 0] += t0;  dsm[L_ + cand0 + 1] += t1;  dsm[L_ + cand0 + 2] += t2;
        }
        __syncthreads();
        if (grp == 2) {
            dsm[cand0 + 0] += s0;
            dsm[L_ + cand0 + 0] += t0;
            if (cand0 + 1 == LSELF_) {
                dsm[LSELF_] = -1.0f;
                dsm[L_ + LSELF_] = -1.0f;
            } else {
                dsm[cand0 + 1] += s1;
                dsm[L_ + cand0 + 1] += t1;
            }
            dsm[cand0 + 2] += s2;
            dsm[L_ + cand0 + 2] += t2;
        }
    } else {
        // ---- General staging (bounds-checked) ----
        for (int idx = tid; idx < TPLANE_; idx += 256) {
            int rr = idx / TSTR_, cc = idx % TSTR_;
            if (rr < Rn && cc < Cn) {
                int gb = (rlo + rr) * W_ + clo + cc;
                #pragma unroll
                for (int s = 0; s < 3; s++) {
                    int ft = clampi(qt + s - WT_, 0, T_ - 1);
                    const float* base = nb + (size_t)ft * C_ * HW_ + gb;
                    tile4[s * TPLANE_ + idx] =
                        make_float4(__ldg(base), __ldg(base + HW_), __ldg(base + 2 * HW_), 0.0f);
                }
                const float* dbase = db + (size_t)qt * C_ * HW_ + gb;
                dtile4[idx] =
                    make_float4(__ldg(dbase), __ldg(dbase + HW_), __ldg(dbase + 2 * HW_), 0.0f);
            }
        }
        __syncthreads();

        // ---- Phase 1 general: per query (reflect/clamp) ----
        #pragma unroll
        for (int qi = 0; qi < 2; qi++) {
            const int qw = qw0 + 4 * qi;
            if (tid < L_) {
                int dti = tid / 81;
                int rm  = tid % 81;
                int dhi = rm / WS_;
                int dwi = rm % WS_;
                int ch = clampi(qh + dhi - 4, 0, H_ - 1);
                int cw = clampi(qw + dwi - 4, 0, W_ - 1);
                int crow[PS_], ccol[PS_], qrow[PS_], qcol[PS_];
                #pragma unroll
                for (int d = 0; d < PS_; d++) {
                    crow[d] = refl(ch + d - 2, H_) - rlo;
                    ccol[d] = refl(cw + d - 2, W_) - clo;
                    qrow[d] = refl(qh + d - 2, H_) - rlo;
                    qcol[d] = refl(qw + d - 2, W_) - clo;
                }
                const ulonglong2* t4 = reinterpret_cast<const ulonglong2*>(tile4);
                u64 acc01 = 0ull, acc2p = 0ull;
                #pragma unroll
                for (int dy = 0; dy < PS_; dy++) {
                    #pragma unroll
                    for (int dx = 0; dx < PS_; dx++) {
                        int qp = 1 * TPLANE_ + qrow[dy] * TSTR_ + qcol[dx];
                        int cp = dti * TPLANE_ + crow[dy] * TSTR_ + ccol[dx];
                        ulonglong2 qv = t4[qp];
                        ulonglong2 cv = t4[cp];
                        u64 d01 = fma2(cv.x, NEG1X2_, qv.x);
                        acc01 = fma2(d01, d01, acc01);
                        u64 d2p = fma2(cv.y, NEG1X2_, qv.y);
                        acc2p = fma2(d2p, d2p, acc2p);
                    }
                }
                float acc = f32x2_sum(acc01) + f32x2_sum(acc2p);
                dsm[qi * L_ + tid] = (tid == LSELF_) ? -1.0f : acc;
            }
        }
    }
    __syncthreads();

    // ---- Phase 2: warps 0 and 1 each select top-K for their query ----
    if (wid < 2) {
        float* dq = dsm + wid * L_;
        for (int k = 0; k < K_; k++) {
            float bd = FLT_MAX;
            int   bi = 1 << 20;
            for (int i = lane; i < L_; i += 32) {
                float v = dq[i];
                if (v < bd) { bd = v; bi = i; }
            }
            #pragma unroll
            for (int off = 16; off; off >>= 1) {
                float od = __shfl_down_sync(0xffffffffu, bd, off);
                int   oi = __shfl_down_sync(0xffffffffu, bi, off);
                if (od < bd || (od == bd && oi < bi)) { bd = od; bi = oi; }
            }
            bi = __shfl_sync(0xffffffffu, bi, 0);
            if (lane == 0) { sel[wid][k] = bi; dq[bi] = FLT_MAX; }
            __syncwarp();
        }
    }
    __syncthreads();

    float part = 0.0f;
    const float* tf = (const float*)tile4;
    const float* df4 = (const float*)dtile4;
    if (interior) {
        if (tid < 2 * (K_ - 1)) {
            int qi = tid / (K_ - 1);
            int k  = tid % (K_ - 1);
            int l = sel[qi][k + 1];
            int dti = l / 81;
            int rm  = l % 81;
            // 7x7 patch top-left for this candidate, in tile pixels
            kbarr[qi][k] = dti * TPLANE_ + (rm / WS_) * TSTR_ + (rm % WS_) + 4 * qi;
        }
        __syncthreads();

        // ---- Phase 3: 2 x 147 work items ----
        for (int i = tid; i < 2 * C_ * PSD_ * PSD_; i += 256) {
            int qi = i / (C_ * PSD_ * PSD_);
            int j  = i % (C_ * PSD_ * PSD_);
            int c   = j / (PSD_ * PSD_);
            int rr  = j % (PSD_ * PSD_);
            int dy0 = rr / PSD_;
            int dx0 = rr % PSD_;
            int mypix = dy0 * TSTR_ + dx0;
            float pd = df4[4 * ((dy0 + 4) * TSTR_ + (dx0 + 4) + 4 * qi) + c];
            #pragma unroll
            for (int k = 0; k < K_ - 1; k++) {
                float pk = tf[4 * (kbarr[qi][k] + mypix) + c];
                float dfv = pd - pk;
                part = fmaf(dfv, dfv, part);
            }
        }
    } else {
        if (tid < 2 * (K_ - 1)) {
            int qi = tid / (K_ - 1);
            int k  = tid % (K_ - 1);
            int qw = qw0 + 4 * qi;
            int l = sel[qi][k + 1];
            int dti = l / 81;
            int rm  = l % 81;
            selt[qi][k] = dti;
            selh[qi][k] = clampi(qh + rm / WS_ - 4, 0, H_ - 1);
            selw[qi][k] = clampi(qw + rm % WS_ - 4, 0, W_ - 1);
        }
        __syncthreads();

        for (int i = tid; i < 2 * (K_ - 1) * C_ * PSD_ * PSD_; i += 256) {
            int qi = i / ((K_ - 1) * C_ * PSD_ * PSD_);
            int r2 = i % ((K_ - 1) * C_ * PSD_ * PSD_);
            int k = r2 / (C_ * PSD_ * PSD_);
            int j = r2 % (C_ * PSD_ * PSD_);
            int c  = j / (PSD_ * PSD_);
            int rr = j % (PSD_ * PSD_);
            int dy = rr / PSD_ - 3;
            int dx = rr % PSD_ - 3;
            int qw = qw0 + 4 * qi;
            int pdp = (refl(qh + dy, H_) - rlo) * TSTR_ + (refl(qw + dx, W_) - clo);
            int pkp = selt[qi][k] * TPLANE_ +
                      (refl(selh[qi][k] + dy, H_) - rlo) * TSTR_ +
                      (refl(selw[qi][k] + dx, W_) - clo);
            float pd = df4[4 * pdp + c];
            float pk = tf[4 * pkp + c];
            float dfv = pd - pk;
            part = fmaf(dfv, dfv, part);
        }
    }

    // ---- Block reduction -> atomic accumulate ----
    #pragma unroll
    for (int off = 16; off; off >>= 1)
        part += __shfl_down_sync(0xffffffffu, part, off);
    if ((tid & 31) == 0) red[tid >> 5] = part;
    __syncthreads();
    if (tid == 0) {
        float s = 0.0f;
        #pragma unroll
        for (int w = 0; w < 8; w++) s += red[w];
        atomicAdd(out, s * (1.0f / (float)(NQ_ * (K_ - 1))));
    }
}

extern "C" void kernel_launch(void* const* d_in, const int* in_sizes, int n_in,
                              void* d_out, int out_size) {
    const float* noisy = (const float*)d_in[0];
    const float* deno  = (const float*)d_in[1];
    // d_in[2] = curr_epoch (unused by the reference computation)
    zero_out_k<<<1, 1>>>((float*)d_out);
    dnls_main_k<<<GRID2_, 256>>>(noisy, deno, (float*)d_out);
}

// round 15
// speedup vs baseline: 1.0164x; 1.0164x over previous
#include <cuda_runtime.h>
#include <float.h>

#define B_ 2
#define T_ 5
#define C_ 3
#define H_ 96
#define W_ 96
#define WS_ 9
#define WT_ 1
#define PS_ 5
#define PSD_ 7
#define K_ 10
#define S0_ 4
#define NH_ (H_ / S0_)
#define NW_ (W_ / S0_)
#define Q_ (T_ * NH_ * NW_)             // 2880
#define L_ ((2 * WT_ + 1) * WS_ * WS_)  // 243
#define LSELF_ 121
#define GRID_ (B_ * Q_)                 // 5760
#define HW_ (H_ * W_)                   // 9216

#define TR_ 15
#define TSTR_ 17
#define TPLANE_ (TR_ * TSTR_)           // 255

typedef unsigned long long u64;
#define NEG1X2_ 0xBF800000BF800000ull   // packed {-1.0f, -1.0f}

__device__ float        g_acc;          // zero-initialized; reset by last block
__device__ unsigned int g_count;        // zero-initialized; reset by last block

__device__ __forceinline__ u64 fma2(u64 a, u64 b, u64 c) {
    u64 d;
    asm("fma.rn.f32x2 %0, %1, %2, %3;" : "=l"(d) : "l"(a), "l"(b), "l"(c));
    return d;
}
__device__ __forceinline__ float f32x2_sum(u64 v) {
    return __uint_as_float((unsigned)(v & 0xffffffffull))
         + __uint_as_float((unsigned)(v >> 32));
}
__device__ __forceinline__ int refl(int i, int n) {
    i = i < 0 ? -i : i;
    return i >= n ? 2 * (n - 1) - i : i;
}
__device__ __forceinline__ int clampi(int i, int lo, int hi) {
    return min(max(i, lo), hi);
}

__global__ __launch_bounds__(256, 6) void dnls_main_k(
    const float* __restrict__ noisy,
    const float* __restrict__ deno,
    float* __restrict__ out)
{
    const int blk = blockIdx.x;
    const int b = blk / Q_;
    const int q = blk % Q_;
    const int qt = q / (NH_ * NW_);
    const int qr = q % (NH_ * NW_);
    const int qh = (qr / NW_) * S0_;
    const int qw = (qr % NW_) * S0_;
    const int tid = threadIdx.x;

    __shared__ float4 tile4 [3 * TPLANE_];   // noisy {c0,c1,c2,0}: [slot][15][17]
    __shared__ float4 dtile4[TPLANE_];       // deno frame qt {c0,c1,c2,0}
    __shared__ float  dsm[L_];
    __shared__ int    sel[K_];
    __shared__ int    kbarr[K_ - 1];
    __shared__ int    selt[K_ - 1], selh[K_ - 1], selw[K_ - 1];
    __shared__ float  red[8];

    const float* nb = noisy + (size_t)b * T_ * C_ * HW_;
    const float* db = deno  + (size_t)b * T_ * C_ * HW_;

    const int rlo = max(0, qh - 7);
    const int clo = max(0, qw - 7);
    const int Rn = min(H_ - 1, qh + 7) - rlo + 1;
    const int Cn = min(W_ - 1, qw + 7) - clo + 1;

    const bool interior = (qh >= 8 && qh <= 88 && qw >= 8 && qw <= 88);

    // per-thread state carried across the phase-1 split (interior path)
    float s0 = 0.0f, s1 = 0.0f, s2 = 0.0f;
    int cand0 = -1;

    if (interior) {
        // ---- Fast staging: 15x15, no bounds checks ----
        if (tid < 240) {
            int rr = tid >> 4, cc = tid & 15;
            if (cc < 15) {
                int gb = (rlo + rr) * W_ + clo + cc;
                int sb = rr * TSTR_ + cc;
                #pragma unroll
                for (int s = 0; s < 3; s++) {
                    int ft = clampi(qt + s - WT_, 0, T_ - 1);
                    const float* base = nb + (size_t)ft * C_ * HW_ + gb;
                    tile4[s * TPLANE_ + sb] =
                        make_float4(__ldg(base), __ldg(base + HW_), __ldg(base + 2 * HW_), 0.0f);
                }
                const float* dbase = db + (size_t)qt * C_ * HW_ + gb;
                dtile4[sb] =
                    make_float4(__ldg(dbase), __ldg(dbase + HW_), __ldg(dbase + 2 * HW_), 0.0f);
            }
        }
        __syncthreads();

        // ---- Phase 1 fast: 1 thread = 3 adjacent-dwi candidates, one u64
        //      channel-half per thread group. 7-wide column window shared. ----
        if (tid < 162) {
            const int grp = (tid < 81) ? 0 : 1;       // 0: {c0,c1}, 1: {c2,pad}
            const int r   = (grp == 0) ? tid : tid - 81;
            const int dti = r / 27;
            const int rr  = r % 27;
            const int dhi = rr / 3;
            const int wg  = rr % 3;                    // dwi in {3wg, 3wg+1, 3wg+2}
            cand0 = dti * 81 + dhi * 9 + 3 * wg;

            const u64* t8 = reinterpret_cast<const u64*>(tile4);
            const int cbase = dti * TPLANE_ + (dhi + 1) * TSTR_ + (3 * wg + 1);
            const int qbase = 1 * TPLANE_ + 5 * TSTR_ + 5;

            u64 a0 = 0ull, a1 = 0ull, a2 = 0ull;
            #pragma unroll
            for (int dy = 0; dy < PS_; dy++) {
                const u64* crow = t8 + 2 * (cbase + dy * TSTR_) + grp;
                const u64* qrow = t8 + 2 * (qbase + dy * TSTR_) + grp;
                u64 v0 = crow[0],  v1 = crow[2],  v2 = crow[4],  v3 = crow[6];
                u64 v4 = crow[8],  v5 = crow[10], v6 = crow[12];
                u64 qv;
                qv = qrow[0];
                { u64 d; d = fma2(v0, NEG1X2_, qv); a0 = fma2(d, d, a0);
                         d = fma2(v1, NEG1X2_, qv); a1 = fma2(d, d, a1);
                         d = fma2(v2, NEG1X2_, qv); a2 = fma2(d, d, a2); }
                qv = qrow[2];
                { u64 d; d = fma2(v1, NEG1X2_, qv); a0 = fma2(d, d, a0);
                         d = fma2(v2, NEG1X2_, qv); a1 = fma2(d, d, a1);
                         d = fma2(v3, NEG1X2_, qv); a2 = fma2(d, d, a2); }
                qv = qrow[4];
                { u64 d; d = fma2(v2, NEG1X2_, qv); a0 = fma2(d, d, a0);
                         d = fma2(v3, NEG1X2_, qv); a1 = fma2(d, d, a1);
                         d = fma2(v4, NEG1X2_, qv); a2 = fma2(d, d, a2); }
                qv = qrow[6];
                { u64 d; d = fma2(v3, NEG1X2_, qv); a0 = fma2(d, d, a0);
                         d = fma2(v4, NEG1X2_, qv); a1 = fma2(d, d, a1);
                         d = fma2(v5, NEG1X2_, qv); a2 = fma2(d, d, a2); }
                qv = qrow[8];
                { u64 d; d = fma2(v4, NEG1X2_, qv); a0 = fma2(d, d, a0);
                         d = fma2(v5, NEG1X2_, qv); a1 = fma2(d, d, a1);
                         d = fma2(v6, NEG1X2_, qv); a2 = fma2(d, d, a2); }
            }
            s0 = f32x2_sum(a0);
            s1 = f32x2_sum(a1);
            s2 = f32x2_sum(a2);
            if (grp == 0) {                    // first halves stored
                dsm[cand0 + 0] = s0;
                dsm[cand0 + 1] = s1;
                dsm[cand0 + 2] = s2;
            }
        }
        __syncthreads();

        // combine second channel-half; fold in the self marker
        if (tid >= 81 && tid < 162) {
            dsm[cand0 + 0] += s0;
            if (cand0 == LSELF_ - 1) dsm[LSELF_] = -1.0f;   // cand0=120 owns 121
            else                     dsm[cand0 + 1] += s1;
            dsm[cand0 + 2] += s2;
        }
    } else {
        // ---- General staging (bounds-checked) ----
        for (int idx = tid; idx < 3 * TPLANE_; idx += 256) {
            int s   = idx / TPLANE_;
            int rem = idx % TPLANE_;
            int rr = rem / TSTR_, cc = rem % TSTR_;
            if (rr < Rn && cc < Cn) {
                int ft = clampi(qt + s - WT_, 0, T_ - 1);
                const float* base = nb + (size_t)ft * C_ * HW_ + (rlo + rr) * W_ + (clo + cc);
                tile4[idx] =
                    make_float4(__ldg(base), __ldg(base + HW_), __ldg(base + 2 * HW_), 0.0f);
            }
        }
        for (int idx = tid; idx < TPLANE_; idx += 256) {
            int rr = idx / TSTR_, cc = idx % TSTR_;
            if (rr < Rn && cc < Cn) {
                const float* dbase = db + (size_t)qt * C_ * HW_ + (rlo + rr) * W_ + (clo + cc);
                dtile4[idx] =
                    make_float4(__ldg(dbase), __ldg(dbase + HW_), __ldg(dbase + 2 * HW_), 0.0f);
            }
        }
        __syncthreads();

        // ---- Phase 1 general (reflect/clamp), LDS.128 per tap ----
        if (tid < L_) {
            int dti = tid / (WS_ * WS_);
            int rem = tid % (WS_ * WS_);
            int dhi = rem / WS_;
            int dwi = rem % WS_;
            int ch = clampi(qh + dhi - WS_ / 2, 0, H_ - 1);
            int cw = clampi(qw + dwi - WS_ / 2, 0, W_ - 1);
            int crow[PS_], ccol[PS_], qrow[PS_], qcol[PS_];
            #pragma unroll
            for (int d = 0; d < PS_; d++) {
                crow[d] = refl(ch + d - PS_ / 2, H_) - rlo;
                ccol[d] = refl(cw + d - PS_ / 2, W_) - clo;
                qrow[d] = refl(qh + d - PS_ / 2, H_) - rlo;
                qcol[d] = refl(qw + d - PS_ / 2, W_) - clo;
            }
            const ulonglong2* t4 = reinterpret_cast<const ulonglong2*>(tile4);
            u64 acc01 = 0ull, acc2p = 0ull;
            #pragma unroll
            for (int dy = 0; dy < PS_; dy++) {
                #pragma unroll
                for (int dx = 0; dx < PS_; dx++) {
                    int qp = 1 * TPLANE_ + qrow[dy] * TSTR_ + qcol[dx];
                    int cp = dti * TPLANE_ + crow[dy] * TSTR_ + ccol[dx];
                    ulonglong2 qv = t4[qp];
                    ulonglong2 cv = t4[cp];
                    u64 d01 = fma2(cv.x, NEG1X2_, qv.x);
                    acc01 = fma2(d01, d01, acc01);
                    u64 d2p = fma2(cv.y, NEG1X2_, qv.y);
                    acc2p = fma2(d2p, d2p, acc2p);
                }
            }
            float acc = f32x2_sum(acc01) + f32x2_sum(acc2p);
            dsm[tid] = (tid == LSELF_) ? -1.0f : acc;
        }
    }
    __syncthreads();

    // ---- Phase 2: K smallest via smem rescan, lowest-index tie-break (warp 0) ----
    if (tid < 32) {
        for (int k = 0; k < K_; k++) {
            float bd = FLT_MAX;
            int   bi = 1 << 20;
            for (int i = tid; i < L_; i += 32) {
                float v = dsm[i];
                if (v < bd) { bd = v; bi = i; }
            }
            #pragma unroll
            for (int off = 16; off; off >>= 1) {
                float od = __shfl_down_sync(0xffffffffu, bd, off);
                int   oi = __shfl_down_sync(0xffffffffu, bi, off);
                if (od < bd || (od == bd && oi < bi)) { bd = od; bi = oi; }
            }
            bi = __shfl_sync(0xffffffffu, bi, 0);
            if (tid == 0) { sel[k] = bi; dsm[bi] = FLT_MAX; }
            __syncwarp();
        }
    }
    __syncthreads();

    float part = 0.0f;
    const float* tf = (const float*)tile4;
    const float* df4 = (const float*)dtile4;
    if (interior) {
        if (tid < K_ - 1) {
            int l = sel[tid + 1];
            int dti = l / (WS_ * WS_);
            int rem = l % (WS_ * WS_);
            kbarr[tid] = dti * TPLANE_ + (rem / WS_) * TSTR_ + (rem % WS_);  // pixel units
        }
        __syncthreads();

        // ---- Phase 3 fast: thread = (c,dy0,dx0), pd loaded once ----
        if (tid < C_ * PSD_ * PSD_) {       // 147 threads
            int c   = tid / (PSD_ * PSD_);
            int rr  = tid % (PSD_ * PSD_);
            int dy0 = rr / PSD_;
            int dx0 = rr % PSD_;
            int mypix = dy0 * TSTR_ + dx0;
            float pd = df4[4 * ((dy0 + 4) * TSTR_ + (dx0 + 4)) + c];
            #pragma unroll
            for (int k = 0; k < K_ - 1; k++) {
                float pk = tf[4 * (kbarr[k] + mypix) + c];
                float dfv = pd - pk;
                part = fmaf(dfv, dfv, part);
            }
        }
    } else {
        if (tid < K_ - 1) {
            int l = sel[tid + 1];
            int dti = l / (WS_ * WS_);
            int rem = l % (WS_ * WS_);
            selt[tid] = dti;
            selh[tid] = clampi(qh + rem / WS_ - WS_ / 2, 0, H_ - 1);
            selw[tid] = clampi(qw + rem % WS_ - WS_ / 2, 0, W_ - 1);
        }
        __syncthreads();

        for (int i = tid; i < (K_ - 1) * C_ * PSD_ * PSD_; i += 256) {
            int k = i / (C_ * PSD_ * PSD_);
            int j = i % (C_ * PSD_ * PSD_);
            int c  = j / (PSD_ * PSD_);
            int rr = j % (PSD_ * PSD_);
            int dy = rr / PSD_ - PSD_ / 2;
            int dx = rr % PSD_ - PSD_ / 2;
            int pdp = (refl(qh + dy, H_) - rlo) * TSTR_ + (refl(qw + dx, W_) - clo);
            int pkp = selt[k] * TPLANE_ +
                      (refl(selh[k] + dy, H_) - rlo) * TSTR_ +
                      (refl(selw[k] + dx, W_) - clo);
            float pd = df4[4 * pdp + c];
            float pk = tf[4 * pkp + c];
            float dfv = pd - pk;
            part = fmaf(dfv, dfv, part);
        }
    }

    // ---- Block reduction -> ordered global accumulate, last block finalizes ----
    #pragma unroll
    for (int off = 16; off; off >>= 1)
        part += __shfl_down_sync(0xffffffffu, part, off);
    if ((tid & 31) == 0) red[tid >> 5] = part;
    __syncthreads();
    if (tid == 0) {
        float s = 0.0f;
        #pragma unroll
        for (int w = 0; w < 8; w++) s += red[w];
        // relaxed accumulate into g_acc (device-scope atomic at L2)
        atomicAdd(&g_acc, s);
        // acq_rel counter tick: release makes our g_acc add visible before the
        // tick; acquire makes all prior ticks' g_acc adds visible to us.
        unsigned int old;
        asm volatile("atom.add.acq_rel.gpu.global.u32 %0, [%1], 1;"
                     : "=r"(old) : "l"(&g_count) : "memory");
        if (old == GRID_ - 1) {
            float total;
            asm volatile("ld.acquire.gpu.global.f32 %0, [%1];"
                         : "=f"(total) : "l"(&g_acc) : "memory");
            out[0] = total * (1.0f / (float)(GRID_ * (K_ - 1)));
            // reset for next graph replay; relaxed gpu-scope stores keep these
            // ordered as atomics (no compiler elision), no L1 flush involved
            asm volatile("st.relaxed.gpu.global.f32 [%0], 0f00000000;"
                         :: "l"(&g_acc) : "memory");
            asm volatile("st.relaxed.gpu.global.u32 [%0], 0;"
                         :: "l"(&g_count) : "memory");
        }
    }
}

extern "C" void kernel_launch(void* const* d_in, const int* in_sizes, int n_in,
                              void* d_out, int out_size) {
    const float* noisy = (const float*)d_in[0];
    const float* deno  = (const float*)d_in[1];
    // d_in[2] = curr_epoch (unused by the reference computation)
    dnls_main_k<<<GRID_, 256>>>(noisy, deno, (float*)d_out);
}

// round 16
// speedup vs baseline: 1.0385x; 1.0218x over previous
#include <cuda_runtime.h>
#include <float.h>

#define B_ 2
#define T_ 5
#define C_ 3
#define H_ 96
#define W_ 96
#define WS_ 9
#define WT_ 1
#define PS_ 5
#define PSD_ 7
#define K_ 10
#define S0_ 4
#define NH_ (H_ / S0_)
#define NW_ (W_ / S0_)
#define Q_ (T_ * NH_ * NW_)             // 2880
#define L_ ((2 * WT_ + 1) * WS_ * WS_)  // 243
#define LSELF_ 121
#define GRID_ (B_ * Q_)                 // 5760
#define HW_ (H_ * W_)                   // 9216

#define TR_ 15
#define TSTR_ 17
#define TPLANE_ (TR_ * TSTR_)           // 255

typedef unsigned long long u64;
#define NEG1X2_ 0xBF800000BF800000ull   // packed {-1.0f, -1.0f}

__device__ __forceinline__ u64 fma2(u64 a, u64 b, u64 c) {
    u64 d;
    asm("fma.rn.f32x2 %0, %1, %2, %3;" : "=l"(d) : "l"(a), "l"(b), "l"(c));
    return d;
}
__device__ __forceinline__ float f32x2_sum(u64 v) {
    return __uint_as_float((unsigned)(v & 0xffffffffull))
         + __uint_as_float((unsigned)(v >> 32));
}
__device__ __forceinline__ int refl(int i, int n) {
    i = i < 0 ? -i : i;
    return i >= n ? 2 * (n - 1) - i : i;
}
__device__ __forceinline__ int clampi(int i, int lo, int hi) {
    return min(max(i, lo), hi);
}

__global__ void zero_out_k(float* out) { out[0] = 0.0f; }

__global__ __launch_bounds__(256, 6) void dnls_main_k(
    const float* __restrict__ noisy,
    const float* __restrict__ deno,
    float* __restrict__ out)
{
    const int blk = blockIdx.x;
    const int b = blk / Q_;
    const int q = blk % Q_;
    const int qt = q / (NH_ * NW_);
    const int qr = q % (NH_ * NW_);
    const int qh = (qr / NW_) * S0_;
    const int qw = (qr % NW_) * S0_;
    const int tid = threadIdx.x;

    __shared__ float4 tile4 [3 * TPLANE_];   // noisy {c0,c1,c2,0}: [slot][15][17]
    __shared__ float4 dtile4[TPLANE_];       // deno frame qt {c0,c1,c2,0}
    __shared__ float  dsm[L_];
    __shared__ int    sel[K_];
    __shared__ int    kbarr[K_ - 1];
    __shared__ int    selt[K_ - 1], selh[K_ - 1], selw[K_ - 1];
    __shared__ float  red[8];

    const float* nb = noisy + (size_t)b * T_ * C_ * HW_;
    const float* db = deno  + (size_t)b * T_ * C_ * HW_;

    const int rlo = max(0, qh - 7);
    const int clo = max(0, qw - 7);
    const int Rn = min(H_ - 1, qh + 7) - rlo + 1;
    const int Cn = min(W_ - 1, qw + 7) - clo + 1;

    const bool interior = (qh >= 8 && qh <= 88 && qw >= 8 && qw <= 88);

    // per-thread state carried across the phase-1 split (interior path)
    float s0 = 0.0f, s1 = 0.0f, s2 = 0.0f;
    int cand0 = -1;

    if (interior) {
        // ---- Fast staging: 15x15, no bounds checks ----
        if (tid < 240) {
            int rr = tid >> 4, cc = tid & 15;
            if (cc < 15) {
                int gb = (rlo + rr) * W_ + clo + cc;
                int sb = rr * TSTR_ + cc;
                #pragma unroll
                for (int s = 0; s < 3; s++) {
                    int ft = clampi(qt + s - WT_, 0, T_ - 1);
                    const float* base = nb + (size_t)ft * C_ * HW_ + gb;
                    tile4[s * TPLANE_ + sb] =
                        make_float4(__ldg(base), __ldg(base + HW_), __ldg(base + 2 * HW_), 0.0f);
                }
                const float* dbase = db + (size_t)qt * C_ * HW_ + gb;
                dtile4[sb] =
                    make_float4(__ldg(dbase), __ldg(dbase + HW_), __ldg(dbase + 2 * HW_), 0.0f);
            }
        }
        __syncthreads();

        // ---- Phase 1 fast: 1 thread = 3 adjacent-dwi candidates, one u64
        //      channel-half per thread group. 7-wide column window shared. ----
        if (tid < 162) {
            const int grp = (tid < 81) ? 0 : 1;       // 0: {c0,c1}, 1: {c2,pad}
            const int r   = (grp == 0) ? tid : tid - 81;
            const int dti = r / 27;
            const int rr  = r % 27;
            const int dhi = rr / 3;
            const int wg  = rr % 3;                    // dwi in {3wg, 3wg+1, 3wg+2}
            cand0 = dti * 81 + dhi * 9 + 3 * wg;

            const u64* t8 = reinterpret_cast<const u64*>(tile4);
            const int cbase = dti * TPLANE_ + (dhi + 1) * TSTR_ + (3 * wg + 1);
            const int qbase = 1 * TPLANE_ + 5 * TSTR_ + 5;

            u64 a0 = 0ull, a1 = 0ull, a2 = 0ull;
            #pragma unroll
            for (int dy = 0; dy < PS_; dy++) {
                const u64* crow = t8 + 2 * (cbase + dy * TSTR_) + grp;
                const u64* qrow = t8 + 2 * (qbase + dy * TSTR_) + grp;
                u64 v0 = crow[0],  v1 = crow[2],  v2 = crow[4],  v3 = crow[6];
                u64 v4 = crow[8],  v5 = crow[10], v6 = crow[12];
                u64 qv;
                qv = qrow[0];
                { u64 d; d = fma2(v0, NEG1X2_, qv); a0 = fma2(d, d, a0);
                         d = fma2(v1, NEG1X2_, qv); a1 = fma2(d, d, a1);
                         d = fma2(v2, NEG1X2_, qv); a2 = fma2(d, d, a2); }
                qv = qrow[2];
                { u64 d; d = fma2(v1, NEG1X2_, qv); a0 = fma2(d, d, a0);
                         d = fma2(v2, NEG1X2_, qv); a1 = fma2(d, d, a1);
                         d = fma2(v3, NEG1X2_, qv); a2 = fma2(d, d, a2); }
                qv = qrow[4];
                { u64 d; d = fma2(v2, NEG1X2_, qv); a0 = fma2(d, d, a0);
                         d = fma2(v3, NEG1X2_, qv); a1 = fma2(d, d, a1);
                         d = fma2(v4, NEG1X2_, qv); a2 = fma2(d, d, a2); }
                qv = qrow[6];
                { u64 d; d = fma2(v3, NEG1X2_, qv); a0 = fma2(d, d, a0);
                         d = fma2(v4, NEG1X2_, qv); a1 = fma2(d, d, a1);
                         d = fma2(v5, NEG1X2_, qv); a2 = fma2(d, d, a2); }
                qv = qrow[8];
                { u64 d; d = fma2(v4, NEG1X2_, qv); a0 = fma2(d, d, a0);
                         d = fma2(v5, NEG1X2_, qv); a1 = fma2(d, d, a1);
                         d = fma2(v6, NEG1X2_, qv); a2 = fma2(d, d, a2); }
            }
            s0 = f32x2_sum(a0);
            s1 = f32x2_sum(a1);
            s2 = f32x2_sum(a2);
            if (grp == 0) {                    // first halves stored
                dsm[cand0 + 0] = s0;
                dsm[cand0 + 1] = s1;
                dsm[cand0 + 2] = s2;
            }
        }
        __syncthreads();

        // combine second channel-half; fold in the self marker
        if (tid >= 81 && tid < 162) {
            dsm[cand0 + 0] += s0;
            if (cand0 == LSELF_ - 1) dsm[LSELF_] = -1.0f;   // cand0=120 owns 121
            else                     dsm[cand0 + 1] += s1;
            dsm[cand0 + 2] += s2;
        }
    } else {
        // ---- General staging (bounds-checked) ----
        for (int idx = tid; idx < 3 * TPLANE_; idx += 256) {
            int s   = idx / TPLANE_;
            int rem = idx % TPLANE_;
            int rr = rem / TSTR_, cc = rem % TSTR_;
            if (rr < Rn && cc < Cn) {
                int ft = clampi(qt + s - WT_, 0, T_ - 1);
                const float* base = nb + (size_t)ft * C_ * HW_ + (rlo + rr) * W_ + (clo + cc);
                tile4[idx] =
                    make_float4(__ldg(base), __ldg(base + HW_), __ldg(base + 2 * HW_), 0.0f);
            }
        }
        for (int idx = tid; idx < TPLANE_; idx += 256) {
            int rr = idx / TSTR_, cc = idx % TSTR_;
            if (rr < Rn && cc < Cn) {
                const float* dbase = db + (size_t)qt * C_ * HW_ + (rlo + rr) * W_ + (clo + cc);
                dtile4[idx] =
                    make_float4(__ldg(dbase), __ldg(dbase + HW_), __ldg(dbase + 2 * HW_), 0.0f);
            }
        }
        __syncthreads();

        // ---- Phase 1 general (reflect/clamp), LDS.128 per tap ----
        if (tid < L_) {
            int dti = tid / (WS_ * WS_);
            int rem = tid % (WS_ * WS_);
            int dhi = rem / WS_;
            int dwi = rem % WS_;
            int ch = clampi(qh + dhi - WS_ / 2, 0, H_ - 1);
            int cw = clampi(qw + dwi - WS_ / 2, 0, W_ - 1);
            int crow[PS_], ccol[PS_], qrow[PS_], qcol[PS_];
            #pragma unroll
            for (int d = 0; d < PS_; d++) {
                crow[d] = refl(ch + d - PS_ / 2, H_) - rlo;
                ccol[d] = refl(cw + d - PS_ / 2, W_) - clo;
                qrow[d] = refl(qh + d - PS_ / 2, H_) - rlo;
                qcol[d] = refl(qw + d - PS_ / 2, W_) - clo;
            }
            const ulonglong2* t4 = reinterpret_cast<const ulonglong2*>(tile4);
            u64 acc01 = 0ull, acc2p = 0ull;
            #pragma unroll
            for (int dy = 0; dy < PS_; dy++) {
                #pragma unroll
                for (int dx = 0; dx < PS_; dx++) {
                    int qp = 1 * TPLANE_ + qrow[dy] * TSTR_ + qcol[dx];
                    int cp = dti * TPLANE_ + crow[dy] * TSTR_ + ccol[dx];
                    ulonglong2 qv = t4[qp];
                    ulonglong2 cv = t4[cp];
                    u64 d01 = fma2(cv.x, NEG1X2_, qv.x);
                    acc01 = fma2(d01, d01, acc01);
                    u64 d2p = fma2(cv.y, NEG1X2_, qv.y);
                    acc2p = fma2(d2p, d2p, acc2p);
                }
            }
            float acc = f32x2_sum(acc01) + f32x2_sum(acc2p);
            dsm[tid] = (tid == LSELF_) ? -1.0f : acc;
        }
    }
    __syncthreads();

    // ---- Phase 2: K smallest via smem rescan, lowest-index tie-break (warp 0) ----
    if (tid < 32) {
        for (int k = 0; k < K_; k++) {
            float bd = FLT_MAX;
            int   bi = 1 << 20;
            for (int i = tid; i < L_; i += 32) {
                float v = dsm[i];
                if (v < bd) { bd = v; bi = i; }
            }
            #pragma unroll
            for (int off = 16; off; off >>= 1) {
                float od = __shfl_down_sync(0xffffffffu, bd, off);
                int   oi = __shfl_down_sync(0xffffffffu, bi, off);
                if (od < bd || (od == bd && oi < bi)) { bd = od; bi = oi; }
            }
            bi = __shfl_sync(0xffffffffu, bi, 0);
            if (tid == 0) { sel[k] = bi; dsm[bi] = FLT_MAX; }
            __syncwarp();
        }
    }
    __syncthreads();

    float part = 0.0f;
    const float* tf = (const float*)tile4;
    const float* df4 = (const float*)dtile4;
    if (interior) {
        if (tid < K_ - 1) {
            int l = sel[tid + 1];
            int dti = l / (WS_ * WS_);
            int rem = l % (WS_ * WS_);
            kbarr[tid] = dti * TPLANE_ + (rem / WS_) * TSTR_ + (rem % WS_);  // pixel units
        }
        __syncthreads();

        // ---- Phase 3 fast: thread = (c,dy0,dx0), pd loaded once ----
        if (tid < C_ * PSD_ * PSD_) {       // 147 threads
            int c   = tid / (PSD_ * PSD_);
            int rr  = tid % (PSD_ * PSD_);
            int dy0 = rr / PSD_;
            int dx0 = rr % PSD_;
            int mypix = dy0 * TSTR_ + dx0;
            float pd = df4[4 * ((dy0 + 4) * TSTR_ + (dx0 + 4)) + c];
            #pragma unroll
            for (int k = 0; k < K_ - 1; k++) {
                float pk = tf[4 * (kbarr[k] + mypix) + c];
                float dfv = pd - pk;
                part = fmaf(dfv, dfv, part);
            }
        }
    } else {
        if (tid < K_ - 1) {
            int l = sel[tid + 1];
            int dti = l / (WS_ * WS_);
            int rem = l % (WS_ * WS_);
            selt[tid] = dti;
            selh[tid] = clampi(qh + rem / WS_ - WS_ / 2, 0, H_ - 1);
            selw[tid] = clampi(qw + rem % WS_ - WS_ / 2, 0, W_ - 1);
        }
        __syncthreads();

        for (int i = tid; i < (K_ - 1) * C_ * PSD_ * PSD_; i += 256) {
            int k = i / (C_ * PSD_ * PSD_);
            int j = i % (C_ * PSD_ * PSD_);
            int c  = j / (PSD_ * PSD_);
            int rr = j % (PSD_ * PSD_);
            int dy = rr / PSD_ - PSD_ / 2;
            int dx = rr % PSD_ - PSD_ / 2;
            int pdp = (refl(qh + dy, H_) - rlo) * TSTR_ + (refl(qw + dx, W_) - clo);
            int pkp = selt[k] * TPLANE_ +
                      (refl(selh[k] + dy, H_) - rlo) * TSTR_ +
                      (refl(selw[k] + dx, W_) - clo);
            float pd = df4[4 * pdp + c];
            float pk = tf[4 * pkp + c];
            float dfv = pd - pk;
            part = fmaf(dfv, dfv, part);
        }
    }

    // ---- Block reduction -> atomic accumulate ----
    #pragma unroll
    for (int off = 16; off; off >>= 1)
        part += __shfl_down_sync(0xffffffffu, part, off);
    if ((tid & 31) == 0) red[tid >> 5] = part;
    __syncthreads();
    if (tid == 0) {
        float s = 0.0f;
        #pragma unroll
        for (int w = 0; w < 8; w++) s += red[w];
        atomicAdd(out, s * (1.0f / (float)(GRID_ * (K_ - 1))));
    }
}

extern "C" void kernel_launch(void* const* d_in, const int* in_sizes, int n_in,
                              void* d_out, int out_size) {
    const float* noisy = (const float*)d_in[0];
    const float* deno  = (const float*)d_in[1];
    // d_in[2] = curr_epoch (unused by the reference computation)
    zero_out_k<<<1, 1>>>((float*)d_out);
    dnls_main_k<<<GRID_, 256>>>(noisy, deno, (float*)d_out);
}

// round 17
// speedup vs baseline: 1.0946x; 1.0540x over previous
#include <cuda_runtime.h>
#include <float.h>

#define B_ 2
#define T_ 5
#define C_ 3
#define H_ 96
#define W_ 96
#define WS_ 9
#define WT_ 1
#define PS_ 5
#define PSD_ 7
#define K_ 10
#define S0_ 4
#define NH_ (H_ / S0_)
#define NW_ (W_ / S0_)
#define Q_ (T_ * NH_ * NW_)             // 2880
#define L_ ((2 * WT_ + 1) * WS_ * WS_)  // 243
#define LSELF_ 121
#define GRID_ (B_ * Q_)                 // 5760
#define HW_ (H_ * W_)                   // 9216

#define TR_ 15
#define TSTR_ 17
#define TPLANE_ (TR_ * TSTR_)           // 255

typedef unsigned long long u64;
#define NEG1X2_ 0xBF800000BF800000ull   // packed {-1.0f, -1.0f}

__device__ __forceinline__ u64 fma2(u64 a, u64 b, u64 c) {
    u64 d;
    asm("fma.rn.f32x2 %0, %1, %2, %3;" : "=l"(d) : "l"(a), "l"(b), "l"(c));
    return d;
}
__device__ __forceinline__ float f32x2_sum(u64 v) {
    return __uint_as_float((unsigned)(v & 0xffffffffull))
         + __uint_as_float((unsigned)(v >> 32));
}
__device__ __forceinline__ int refl(int i, int n) {
    i = i < 0 ? -i : i;
    return i >= n ? 2 * (n - 1) - i : i;
}
__device__ __forceinline__ int clampi(int i, int lo, int hi) {
    return min(max(i, lo), hi);
}

__global__ void zero_out_k(float* out) { out[0] = 0.0f; }

__global__ __launch_bounds__(256, 7) void dnls_main_k(
    const float* __restrict__ noisy,
    const float* __restrict__ deno,
    float* __restrict__ out)
{
    const int blk = blockIdx.x;
    const int b = blk / Q_;
    const int q = blk % Q_;
    const int qt = q / (NH_ * NW_);
    const int qr = q % (NH_ * NW_);
    const int qh = (qr / NW_) * S0_;
    const int qw = (qr % NW_) * S0_;
    const int tid = threadIdx.x;

    __shared__ float4 tile4 [3 * TPLANE_];   // noisy {c0,c1,c2,0}: [slot][15][17]
    __shared__ float4 dtile4[TPLANE_];       // deno frame qt {c0,c1,c2,0}
    __shared__ float  dsm[L_];
    __shared__ int    sel[K_];
    __shared__ int    kbarr[K_ - 1];
    __shared__ int    selt[K_ - 1], selh[K_ - 1], selw[K_ - 1];
    __shared__ float  red[8];

    const float* nb = noisy + (size_t)b * T_ * C_ * HW_;
    const float* db = deno  + (size_t)b * T_ * C_ * HW_;

    const int rlo = max(0, qh - 7);
    const int clo = max(0, qw - 7);
    const int Rn = min(H_ - 1, qh + 7) - rlo + 1;
    const int Cn = min(W_ - 1, qw + 7) - clo + 1;

    const bool interior = (qh >= 8 && qh <= 88 && qw >= 8 && qw <= 88);

    // per-thread state carried across the phase-1 split (interior path)
    float s0 = 0.0f, s1 = 0.0f, s2 = 0.0f;
    int cand0 = -1;

    if (interior) {
        // ---- Fast staging: 15x15, no bounds checks ----
        if (tid < 240) {
            int rr = tid >> 4, cc = tid & 15;
            if (cc < 15) {
                int gb = (rlo + rr) * W_ + clo + cc;
                int sb = rr * TSTR_ + cc;
                #pragma unroll
                for (int s = 0; s < 3; s++) {
                    int ft = clampi(qt + s - WT_, 0, T_ - 1);
                    const float* base = nb + (size_t)ft * C_ * HW_ + gb;
                    tile4[s * TPLANE_ + sb] =
                        make_float4(__ldg(base), __ldg(base + HW_), __ldg(base + 2 * HW_), 0.0f);
                }
                const float* dbase = db + (size_t)qt * C_ * HW_ + gb;
                dtile4[sb] =
                    make_float4(__ldg(dbase), __ldg(dbase + HW_), __ldg(dbase + 2 * HW_), 0.0f);
            }
        }
        __syncthreads();

        // ---- Phase 1 fast: 1 thread = 3 adjacent-dwi candidates, one u64
        //      channel-half per thread group. 7-wide column window shared. ----
        if (tid < 162) {
            const int grp = (tid < 81) ? 0 : 1;       // 0: {c0,c1}, 1: {c2,pad}
            const int r   = (grp == 0) ? tid : tid - 81;
            const int dti = r / 27;
            const int rr  = r % 27;
            const int dhi = rr / 3;
            const int wg  = rr % 3;                    // dwi in {3wg, 3wg+1, 3wg+2}
            cand0 = dti * 81 + dhi * 9 + 3 * wg;

            const u64* t8 = reinterpret_cast<const u64*>(tile4);
            const int cbase = dti * TPLANE_ + (dhi + 1) * TSTR_ + (3 * wg + 1);
            const int qbase = 1 * TPLANE_ + 5 * TSTR_ + 5;

            u64 a0 = 0ull, a1 = 0ull, a2 = 0ull;
            #pragma unroll
            for (int dy = 0; dy < PS_; dy++) {
                const u64* crow = t8 + 2 * (cbase + dy * TSTR_) + grp;
                const u64* qrow = t8 + 2 * (qbase + dy * TSTR_) + grp;
                u64 v0 = crow[0],  v1 = crow[2],  v2 = crow[4],  v3 = crow[6];
                u64 v4 = crow[8],  v5 = crow[10], v6 = crow[12];
                u64 qv;
                qv = qrow[0];
                { u64 d; d = fma2(v0, NEG1X2_, qv); a0 = fma2(d, d, a0);
                         d = fma2(v1, NEG1X2_, qv); a1 = fma2(d, d, a1);
                         d = fma2(v2, NEG1X2_, qv); a2 = fma2(d, d, a2); }
                qv = qrow[2];
                { u64 d; d = fma2(v1, NEG1X2_, qv); a0 = fma2(d, d, a0);
                         d = fma2(v2, NEG1X2_, qv); a1 = fma2(d, d, a1);
                         d = fma2(v3, NEG1X2_, qv); a2 = fma2(d, d, a2); }
                qv = qrow[4];
                { u64 d; d = fma2(v2, NEG1X2_, qv); a0 = fma2(d, d, a0);
                         d = fma2(v3, NEG1X2_, qv); a1 = fma2(d, d, a1);
                         d = fma2(v4, NEG1X2_, qv); a2 = fma2(d, d, a2); }
                qv = qrow[6];
                { u64 d; d = fma2(v3, NEG1X2_, qv); a0 = fma2(d, d, a0);
                         d = fma2(v4, NEG1X2_, qv); a1 = fma2(d, d, a1);
                         d = fma2(v5, NEG1X2_, qv); a2 = fma2(d, d, a2); }
                qv = qrow[8];
                { u64 d; d = fma2(v4, NEG1X2_, qv); a0 = fma2(d, d, a0);
                         d = fma2(v5, NEG1X2_, qv); a1 = fma2(d, d, a1);
                         d = fma2(v6, NEG1X2_, qv); a2 = fma2(d, d, a2); }
            }
            s0 = f32x2_sum(a0);
            s1 = f32x2_sum(a1);
            s2 = f32x2_sum(a2);
            if (grp == 0) {                    // first halves stored
                dsm[cand0 + 0] = s0;
                dsm[cand0 + 1] = s1;
                dsm[cand0 + 2] = s2;
            }
        }
        __syncthreads();

        // combine second channel-half; fold in the self marker
        if (tid >= 81 && tid < 162) {
            dsm[cand0 + 0] += s0;
            if (cand0 == LSELF_ - 1) dsm[LSELF_] = -1.0f;   // cand0=120 owns 121
            else                     dsm[cand0 + 1] += s1;
            dsm[cand0 + 2] += s2;
        }
    } else {
        // ---- General staging (bounds-checked) ----
        for (int idx = tid; idx < 3 * TPLANE_; idx += 256) {
            int s   = idx / TPLANE_;
            int rem = idx % TPLANE_;
            int rr = rem / TSTR_, cc = rem % TSTR_;
            if (rr < Rn && cc < Cn) {
                int ft = clampi(qt + s - WT_, 0, T_ - 1);
                const float* base = nb + (size_t)ft * C_ * HW_ + (rlo + rr) * W_ + (clo + cc);
                tile4[idx] =
                    make_float4(__ldg(base), __ldg(base + HW_), __ldg(base + 2 * HW_), 0.0f);
            }
        }
        for (int idx = tid; idx < TPLANE_; idx += 256) {
            int rr = idx / TSTR_, cc = idx % TSTR_;
            if (rr < Rn && cc < Cn) {
                const float* dbase = db + (size_t)qt * C_ * HW_ + (rlo + rr) * W_ + (clo + cc);
                dtile4[idx] =
                    make_float4(__ldg(dbase), __ldg(dbase + HW_), __ldg(dbase + 2 * HW_), 0.0f);
            }
        }
        __syncthreads();

        // ---- Phase 1 general (reflect/clamp), LDS.128 per tap ----
        if (tid < L_) {
            int dti = tid / (WS_ * WS_);
            int rem = tid % (WS_ * WS_);
            int dhi = rem / WS_;
            int dwi = rem % WS_;
            int ch = clampi(qh + dhi - WS_ / 2, 0, H_ - 1);
            int cw = clampi(qw + dwi - WS_ / 2, 0, W_ - 1);
            int crow[PS_], ccol[PS_], qrow[PS_], qcol[PS_];
            #pragma unroll
            for (int d = 0; d < PS_; d++) {
                crow[d] = refl(ch + d - PS_ / 2, H_) - rlo;
                ccol[d] = refl(cw + d - PS_ / 2, W_) - clo;
                qrow[d] = refl(qh + d - PS_ / 2, H_) - rlo;
                qcol[d] = refl(qw + d - PS_ / 2, W_) - clo;
            }
            const ulonglong2* t4 = reinterpret_cast<const ulonglong2*>(tile4);
            u64 acc01 = 0ull, acc2p = 0ull;
            #pragma unroll
            for (int dy = 0; dy < PS_; dy++) {
                #pragma unroll
                for (int dx = 0; dx < PS_; dx++) {
                    int qp = 1 * TPLANE_ + qrow[dy] * TSTR_ + qcol[dx];
                    int cp = dti * TPLANE_ + crow[dy] * TSTR_ + ccol[dx];
                    ulonglong2 qv = t4[qp];
                    ulonglong2 cv = t4[cp];
                    u64 d01 = fma2(cv.x, NEG1X2_, qv.x);
                    acc01 = fma2(d01, d01, acc01);
                    u64 d2p = fma2(cv.y, NEG1X2_, qv.y);
                    acc2p = fma2(d2p, d2p, acc2p);
                }
            }
            float acc = f32x2_sum(acc01) + f32x2_sum(acc2p);
            dsm[tid] = (tid == LSELF_) ? -1.0f : acc;
        }
    }
    __syncthreads();

    // ---- Phase 2: K smallest via smem rescan, lowest-index tie-break (warp 0) ----
    if (tid < 32) {
        for (int k = 0; k < K_; k++) {
            float bd = FLT_MAX;
            int   bi = 1 << 20;
            for (int i = tid; i < L_; i += 32) {
                float v = dsm[i];
                if (v < bd) { bd = v; bi = i; }
            }
            #pragma unroll
            for (int off = 16; off; off >>= 1) {
                float od = __shfl_down_sync(0xffffffffu, bd, off);
                int   oi = __shfl_down_sync(0xffffffffu, bi, off);
                if (od < bd || (od == bd && oi < bi)) { bd = od; bi = oi; }
            }
            bi = __shfl_sync(0xffffffffu, bi, 0);
            if (tid == 0) { sel[k] = bi; dsm[bi] = FLT_MAX; }
            __syncwarp();
        }
    }
    __syncthreads();

    float part = 0.0f;
    const float* tf = (const float*)tile4;
    const float* df4 = (const float*)dtile4;
    if (interior) {
        if (tid < K_ - 1) {
            int l = sel[tid + 1];
            int dti = l / (WS_ * WS_);
            int rem = l % (WS_ * WS_);
            kbarr[tid] = dti * TPLANE_ + (rem / WS_) * TSTR_ + (rem % WS_);  // pixel units
        }
        __syncthreads();

        // ---- Phase 3 fast: thread = (c,dy0,dx0), pd loaded once ----
        if (tid < C_ * PSD_ * PSD_) {       // 147 threads
            int c   = tid / (PSD_ * PSD_);
            int rr  = tid % (PSD_ * PSD_);
            int dy0 = rr / PSD_;
            int dx0 = rr % PSD_;
            int mypix = dy0 * TSTR_ + dx0;
            float pd = df4[4 * ((dy0 + 4) * TSTR_ + (dx0 + 4)) + c];
            #pragma unroll
            for (int k = 0; k < K_ - 1; k++) {
                float pk = tf[4 * (kbarr[k] + mypix) + c];
                float dfv = pd - pk;
                part = fmaf(dfv, dfv, part);
            }
        }
    } else {
        if (tid < K_ - 1) {
            int l = sel[tid + 1];
            int dti = l / (WS_ * WS_);
            int rem = l % (WS_ * WS_);
            selt[tid] = dti;
            selh[tid] = clampi(qh + rem / WS_ - WS_ / 2, 0, H_ - 1);
            selw[tid] = clampi(qw + rem % WS_ - WS_ / 2, 0, W_ - 1);
        }
        __syncthreads();

        for (int i = tid; i < (K_ - 1) * C_ * PSD_ * PSD_; i += 256) {
            int k = i / (C_ * PSD_ * PSD_);
            int j = i % (C_ * PSD_ * PSD_);
            int c  = j / (PSD_ * PSD_);
            int rr = j % (PSD_ * PSD_);
            int dy = rr / PSD_ - PSD_ / 2;
            int dx = rr % PSD_ - PSD_ / 2;
            int pdp = (refl(qh + dy, H_) - rlo) * TSTR_ + (refl(qw + dx, W_) - clo);
            int pkp = selt[k] * TPLANE_ +
                      (refl(selh[k] + dy, H_) - rlo) * TSTR_ +
                      (refl(selw[k] + dx, W_) - clo);
            float pd = df4[4 * pdp + c];
            float pk = tf[4 * pkp + c];
            float dfv = pd - pk;
            part = fmaf(dfv, dfv, part);
        }
    }

    // ---- Block reduction -> atomic accumulate ----
    #pragma unroll
    for (int off = 16; off; off >>= 1)
        part += __shfl_down_sync(0xffffffffu, part, off);
    if ((tid & 31) == 0) red[tid >> 5] = part;
    __syncthreads();
    if (tid == 0) {
        float s = 0.0f;
        #pragma unroll
        for (int w = 0; w < 8; w++) s += red[w];
        atomicAdd(out, s * (1.0f / (float)(GRID_ * (K_ - 1))));
    }
}

extern "C" void kernel_launch(void* const* d_in, const int* in_sizes, int n_in,
                              void* d_out, int out_size) {
    const float* noisy = (const float*)d_in[0];
    const float* deno  = (const float*)d_in[1];
    // d_in[2] = curr_epoch (unused by the reference computation)
    zero_out_k<<<1, 1>>>((float*)d_out);
    dnls_main_k<<<GRID_, 256>>>(noisy, deno, (float*)d_out);
}